// round 1
// baseline (speedup 1.0000x reference)
#include <cuda_runtime.h>
#include <cuda_bf16.h>

#define IN_DIM   512
#define BATCH    8192
#define GRID_NUM 48
#define KDEG     3
#define NCOEF    (GRID_NUM + KDEG)   // 51 basis functions per dim
#define NKNOT    (GRID_NUM + 1)      // 49 grid columns per dim

// Scratch: per-dim grid origin and inverse spacing (alloc-free __device__ globals).
__device__ float g_lo[IN_DIM];
__device__ float g_invh[IN_DIM];

__global__ void precompute_grid_kernel(const float* __restrict__ grid) {
    int i = blockIdx.x * blockDim.x + threadIdx.x;
    if (i < IN_DIM) {
        float lo = grid[i * NKNOT];
        float hi = grid[i * NKNOT + GRID_NUM];
        g_lo[i]   = lo;
        g_invh[i] = (float)GRID_NUM / (hi - lo);
    }
}

// One thread = one float4 = 4 consecutive input dims of one batch row.
// x,y layout: [BATCH, IN_DIM] row-major, IN_DIM divisible by 4 -> i index = (4*idx) & 511.
__global__ __launch_bounds__(256) void bspline_kernel(
    const float4* __restrict__ x4,
    const float*  __restrict__ coef,
    float4* __restrict__ y4)
{
    int idx = blockIdx.x * blockDim.x + threadIdx.x;
    float4 xv = x4[idx];
    int ibase = (idx * 4) & (IN_DIM - 1);

    float xs[4] = {xv.x, xv.y, xv.z, xv.w};
    float out[4];

    #pragma unroll
    for (int j = 0; j < 4; ++j) {
        int i = ibase + j;
        float t = (xs[j] - g_lo[i]) * g_invh[i];
        int cell = (int)floorf(t);
        cell = max(0, min(cell, GRID_NUM - 1));   // keep cell+3 <= 50 in-row
        float u = t - (float)cell;
        float v = 1.0f - u;

        // Uniform cubic B-spline weights (partition of unity).
        float w0 = v * v * v * (1.0f / 6.0f);
        float w3 = u * u * u * (1.0f / 6.0f);
        float w1 = (1.0f / 6.0f) * (3.0f * u * u * (u - 2.0f) + 4.0f);
        float w2 = 1.0f - w0 - w1 - w3;

        const float* c = coef + i * NCOEF + cell;  // 4 scattered L1-hit loads
        out[j] = w0 * c[0] + w1 * c[1] + w2 * c[2] + w3 * c[3];
    }

    y4[idx] = make_float4(out[0], out[1], out[2], out[3]);
}

extern "C" void kernel_launch(void* const* d_in, const int* in_sizes, int n_in,
                              void* d_out, int out_size) {
    const float* x    = (const float*)d_in[0];
    const float* grid = (const float*)d_in[1];
    const float* coef = (const float*)d_in[2];
    float* y = (float*)d_out;

    precompute_grid_kernel<<<(IN_DIM + 255) / 256, 256>>>(grid);

    const int n4 = (BATCH * IN_DIM) / 4;   // 1,048,576 float4s
    bspline_kernel<<<n4 / 256, 256>>>((const float4*)x, coef, (float4*)y);
}

// round 2
// speedup vs baseline: 1.7480x; 1.7480x over previous
#include <cuda_runtime.h>
#include <cuda_bf16.h>

#define IN_DIM   512
#define BATCH    8192
#define GRID_NUM 48
#define NCOEF    (GRID_NUM + 3)   // 51
#define NKNOT    (GRID_NUM + 1)   // 49
#define TILE     128              // dims per block
#define THREADS  256              // 2 rows per block iteration
#define YBLOCKS  148

__global__ __launch_bounds__(THREADS) void bspline_kernel(
    const float* __restrict__ x,
    const float* __restrict__ grid,
    const float* __restrict__ coef,
    float* __restrict__ y)
{
    __shared__ float s_coef[TILE * NCOEF];   // 26112 B, lane stride 51 -> conflict-free
    __shared__ float s_lo[TILE];
    __shared__ float s_invh[TILE];

    const int tid  = threadIdx.x;
    const int dim0 = blockIdx.x * TILE;

    // Stage this block's coef slice (contiguous 26112 B) + per-dim grid params.
    const float* csrc = coef + dim0 * NCOEF;
    for (int k = tid; k < TILE * NCOEF; k += THREADS) s_coef[k] = csrc[k];
    if (tid < TILE) {
        int i = dim0 + tid;
        float lo = grid[i * NKNOT];
        float hi = grid[i * NKNOT + GRID_NUM];
        s_lo[tid]   = lo;
        s_invh[tid] = (float)GRID_NUM / (hi - lo);
    }
    __syncthreads();

    const int d    = tid & (TILE - 1);       // lane -> consecutive dims
    const int rofs = tid >> 7;               // 0 or 1: row within iteration
    const float lo   = s_lo[d];
    const float invh = s_invh[d];
    const float* crow = s_coef + d * NCOEF;

    const int stride = YBLOCKS * 2;          // rows advanced per block iteration
    const int col = dim0 + d;

    for (int b = blockIdx.y * 2 + rofs; b < BATCH; b += 4 * stride) {
        float xv[4];
        float res[4];
        #pragma unroll
        for (int q = 0; q < 4; ++q) {        // batch the streaming loads (MLP)
            int bb = b + q * stride;
            xv[q] = (bb < BATCH) ? x[bb * IN_DIM + col] : 0.0f;
        }
        #pragma unroll
        for (int q = 0; q < 4; ++q) {
            float t = (xv[q] - lo) * invh;
            int cell = (int)floorf(t);
            cell = max(0, min(cell, GRID_NUM - 1));
            float u = t - (float)cell;
            float v = 1.0f - u;

            float w0 = v * v * v * (1.0f / 6.0f);
            float w3 = u * u * u * (1.0f / 6.0f);
            float w1 = (1.0f / 6.0f) * (3.0f * u * u * (u - 2.0f) + 4.0f);
            float w2 = 1.0f - w0 - w1 - w3;

            const float* c = crow + cell;    // 4 conflict-free LDS
            res[q] = w0 * c[0] + w1 * c[1] + w2 * c[2] + w3 * c[3];
        }
        #pragma unroll
        for (int q = 0; q < 4; ++q) {
            int bb = b + q * stride;
            if (bb < BATCH) y[bb * IN_DIM + col] = res[q];
        }
    }
}

extern "C" void kernel_launch(void* const* d_in, const int* in_sizes, int n_in,
                              void* d_out, int out_size) {
    const float* x    = (const float*)d_in[0];
    const float* grid = (const float*)d_in[1];
    const float* coef = (const float*)d_in[2];
    float* y = (float*)d_out;

    dim3 g(IN_DIM / TILE, YBLOCKS);          // 4 x 148 = 592 blocks
    bspline_kernel<<<g, THREADS>>>(x, grid, coef, y);
}

// round 3
// speedup vs baseline: 1.9584x; 1.1204x over previous
#include <cuda_runtime.h>
#include <cuda_bf16.h>

#define IN_DIM   512
#define BATCH    8192
#define GRID_NUM 48
#define NCOEF    (GRID_NUM + 3)   // 51
#define NKNOT    (GRID_NUM + 1)   // 49
#define TILE     128              // dims per block
#define THREADS  256              // 2 rows per block iteration
#define YBLOCKS  256              // rows covered per step = 512 -> 16 rows/thread exactly

// One-shot transposed coef [c][dim] + per-dim grid params (alloc-free __device__ scratch).
__device__ float g_coef_t[NCOEF * IN_DIM];
__device__ float g_lo[IN_DIM];
__device__ float g_invh[IN_DIM];

__global__ void prep_kernel(const float* __restrict__ grid,
                            const float* __restrict__ coef) {
    int k = blockIdx.x * blockDim.x + threadIdx.x;
    if (k < IN_DIM * NCOEF) {
        int d = k / NCOEF, c = k % NCOEF;
        g_coef_t[c * IN_DIM + d] = coef[k];      // coalesced read, scattered write (one-shot)
    }
    if (k < IN_DIM) {
        float lo = grid[k * NKNOT];
        float hi = grid[k * NKNOT + GRID_NUM];
        g_lo[k]   = lo;
        g_invh[k] = (float)GRID_NUM / (hi - lo);
    }
}

__global__ __launch_bounds__(THREADS) void bspline_kernel(
    const float* __restrict__ x,
    float* __restrict__ y)
{
    __shared__ float s_t[NCOEF * TILE];          // [c][d], bank = d%32 -> conflict-free
    __shared__ float s_lo[TILE];
    __shared__ float s_invh[TILE];

    const int tid  = threadIdx.x;
    const int dim0 = blockIdx.x * TILE;

    // Stage transposed slice: coalesced LDG, conflict-free STS (d is fast axis).
    #pragma unroll 4
    for (int k = tid; k < NCOEF * TILE; k += THREADS) {
        int c = k >> 7, d = k & (TILE - 1);
        s_t[k] = g_coef_t[c * IN_DIM + dim0 + d];
    }
    if (tid < TILE) {
        s_lo[tid]   = g_lo[dim0 + tid];
        s_invh[tid] = g_invh[dim0 + tid];
    }
    __syncthreads();

    const int d    = tid & (TILE - 1);
    const int rofs = tid >> 7;                   // 0/1
    const float lo   = s_lo[d];
    const float invh = s_invh[d];
    const int col = dim0 + d;
    const int b0  = blockIdx.y * 2 + rofs;

    #pragma unroll
    for (int g = 0; g < 4; ++g) {
        float xv[4], res[4];
        #pragma unroll
        for (int q = 0; q < 4; ++q)              // batch streaming loads (MLP)
            xv[q] = x[(b0 + (g * 4 + q) * (YBLOCKS * 2)) * IN_DIM + col];
        #pragma unroll
        for (int q = 0; q < 4; ++q) {
            float t = (xv[q] - lo) * invh;
            int cell = (int)floorf(t);
            cell = max(0, min(cell, GRID_NUM - 1));
            float u = t - (float)cell;
            float v = 1.0f - u;

            float w0 = v * v * v * (1.0f / 6.0f);
            float w3 = u * u * u * (1.0f / 6.0f);
            float w1 = (1.0f / 6.0f) * (3.0f * u * u * (u - 2.0f) + 4.0f);
            float w2 = 1.0f - w0 - w1 - w3;

            const float* c = s_t + cell * TILE + d;   // conflict-free LDS x4
            res[q] = w0 * c[0] + w1 * c[TILE] + w2 * c[2 * TILE] + w3 * c[3 * TILE];
        }
        #pragma unroll
        for (int q = 0; q < 4; ++q)
            y[(b0 + (g * 4 + q) * (YBLOCKS * 2)) * IN_DIM + col] = res[q];
    }
}

extern "C" void kernel_launch(void* const* d_in, const int* in_sizes, int n_in,
                              void* d_out, int out_size) {
    const float* x    = (const float*)d_in[0];
    const float* grid = (const float*)d_in[1];
    const float* coef = (const float*)d_in[2];
    float* y = (float*)d_out;

    prep_kernel<<<(IN_DIM * NCOEF + 255) / 256, 256>>>(grid, coef);

    dim3 g(IN_DIM / TILE, YBLOCKS);              // 4 x 256 = 1024 blocks
    bspline_kernel<<<g, THREADS>>>(x, y);
}